// round 13
// baseline (speedup 1.0000x reference)
#include <cuda_runtime.h>
#include <cuda_bf16.h>
#include <cuda_fp16.h>
#include <cstdint>

#define N_NODES 100000
#define N_EDGES 1600000
#define IN_DIM 128
#define HID_DIM 64
#define OUT_DIM 128

#define SCAN_NB 98  // ceil(100000/1024)
#define SCAN_FLAG (1 << 30)

// ---------------------------------------------------------------------------
// Device scratch (no allocations allowed).
// NOTE: g_cnt and g_bsum rely on zero-at-exit discipline: they are zero at
// module load, and every launch re-zeroes them (aggregate clears g_cnt,
// bin clears g_bsum) so each graph replay sees the same initial state.
// ---------------------------------------------------------------------------
__device__ __half g_h16[N_NODES * HID_DIM];   // h_scaled = (x@Wc)*dinv, fp16
__device__ __half g_agg16[N_NODES * HID_DIM]; // relu(agg*dinv + bc), fp16
__device__ float  g_dinv[N_NODES];
__device__ int    g_cnt[N_NODES];             // in-degree (no self-loop)
__device__ int    g_off[N_NODES];             // CSR row start
__device__ int    g_slot[N_EDGES];            // per-edge slot within dst row
__device__ int    g_bsum[SCAN_NB];            // lookback aggregates (flag bit 30)
__device__ int    g_srcbin[N_EDGES];          // CSR: src per in-edge, by dst

// Prepacked B fragments for mma.sync m16n8k16 (fp16 hi/lo for both GEMMs).
__device__ uint2 g_WcB_hi[8 * 8 * 32];
__device__ uint2 g_WcB_lo[8 * 8 * 32];
__device__ uint2 g_WlB_hi[4 * 16 * 32];
__device__ uint2 g_WlB_lo[4 * 16 * 32];

// ---------------------------------------------------------------------------
// Helpers
// ---------------------------------------------------------------------------
__device__ __forceinline__ void split2h(float a, float b, uint32_t& hi, uint32_t& lo) {
    __half ha = __float2half_rn(a);
    __half hb = __float2half_rn(b);
    __half la = __float2half_rn(a - __half2float(ha));
    __half lb = __float2half_rn(b - __half2float(hb));
    __half2 hpack = __halves2half2(ha, hb);
    __half2 lpack = __halves2half2(la, lb);
    hi = *reinterpret_cast<uint32_t*>(&hpack);
    lo = *reinterpret_cast<uint32_t*>(&lpack);
}

__device__ __forceinline__ void mma_f16(float* c, uint32_t a0, uint32_t a1,
                                        uint32_t a2, uint32_t a3,
                                        uint32_t b0, uint32_t b1) {
    asm volatile(
        "mma.sync.aligned.m16n8k16.row.col.f32.f16.f16.f32 "
        "{%0,%1,%2,%3}, {%4,%5,%6,%7}, {%8,%9}, {%0,%1,%2,%3};"
        : "+f"(c[0]), "+f"(c[1]), "+f"(c[2]), "+f"(c[3])
        : "r"(a0), "r"(a1), "r"(a2), "r"(a3), "r"(b0), "r"(b1));
}

// Weight fragment packing (streamB; independent of everything else)
__global__ void k_initw(const float* __restrict__ Wc, const float* __restrict__ Wl) {
    int t = blockIdx.x * blockDim.x + threadIdx.x;
    if (t < 2048) {  // Wc: 8 kt x 8 nt x 32 lanes
        int lane = t & 31, nt = (t >> 5) & 7, kt = t >> 8;
        int k0 = kt * 16 + (lane & 3) * 2;
        int n = nt * 8 + (lane >> 2);
        uint2 hi, lo;
        split2h(Wc[k0 * HID_DIM + n], Wc[(k0 + 1) * HID_DIM + n], hi.x, lo.x);
        split2h(Wc[(k0 + 8) * HID_DIM + n], Wc[(k0 + 9) * HID_DIM + n], hi.y, lo.y);
        g_WcB_hi[t] = hi;
        g_WcB_lo[t] = lo;
    } else if (t < 4096) {  // Wl: 4 kt x 16 nt x 32 lanes
        int u = t - 2048;
        int lane = u & 31, nt = (u >> 5) & 15, kt = u >> 9;
        int k0 = kt * 16 + (lane & 3) * 2;
        int n = nt * 8 + (lane >> 2);
        uint2 hi, lo;
        split2h(Wl[k0 * OUT_DIM + n], Wl[(k0 + 1) * OUT_DIM + n], hi.x, lo.x);
        split2h(Wl[(k0 + 8) * OUT_DIM + n], Wl[(k0 + 9) * OUT_DIM + n], hi.y, lo.y);
        g_WlB_hi[u] = hi;
        g_WlB_lo[u] = lo;
    }
}

// Count in-degrees AND record each edge's slot within its dst row.
// (g_cnt arrives zeroed: module-load zero-init, then aggregate re-zeroes it.)
__global__ void k_count(const int* __restrict__ dst) {
    int e4 = blockIdx.x * blockDim.x + threadIdx.x;
    if (e4 >= N_EDGES / 4) return;
    int4 d = ((const int4*)dst)[e4];
    int4 s;
    s.x = atomicAdd(&g_cnt[d.x], 1);
    s.y = atomicAdd(&g_cnt[d.y], 1);
    s.z = atomicAdd(&g_cnt[d.z], 1);
    s.w = atomicAdd(&g_cnt[d.w], 1);
    ((int4*)g_slot)[e4] = s;
}

// ---------------------------------------------------------------------------
// Fused exclusive scan (decoupled lookback) + dinv.
// ---------------------------------------------------------------------------
__global__ __launch_bounds__(256) void k_scan_fused() {
    __shared__ int sh[256];
    int t = threadIdx.x, b = blockIdx.x;
    int base = b * 1024 + t * 4;
    int v[4];
    #pragma unroll
    for (int i = 0; i < 4; i++)
        v[i] = (base + i < N_NODES) ? g_cnt[base + i] : 0;
    int s = v[0] + v[1] + v[2] + v[3];
    sh[t] = s;
    __syncthreads();
    #pragma unroll
    for (int off = 1; off < 256; off <<= 1) {
        int add = (t >= off) ? sh[t - off] : 0;
        __syncthreads();
        sh[t] += add;
        __syncthreads();
    }
    if (t == 255) atomicExch(&g_bsum[b], sh[255] | SCAN_FLAG);
    int ex = sh[t] - s;  // exclusive prefix within block

    int part = 0;
    if (t < b) {
        int val;
        do { val = atomicAdd(&g_bsum[t], 0); } while (!(val & SCAN_FLAG));
        part = val & ~SCAN_FLAG;
    }
    __syncthreads();
    sh[t] = part;
    __syncthreads();
    #pragma unroll
    for (int off = 128; off >= 1; off >>= 1) {
        if (t < off) sh[t] += sh[t + off];
        __syncthreads();
    }
    int boff = sh[0];

    int run = ex + boff;
    #pragma unroll
    for (int i = 0; i < 4; i++) {
        int idx = base + i;
        if (idx < N_NODES) {
            g_off[idx] = run;
            g_dinv[idx] = rsqrtf((float)(v[i] + 1));
            run += v[i];
        }
    }
}

// Bin edges by dst — atomic-free: pos = off[dst] + slot.
// Also clears g_bsum for the next replay (scan has fully completed by now).
__global__ void k_bin(const int* __restrict__ ei) {
    if (blockIdx.x == 0 && threadIdx.x < SCAN_NB) g_bsum[threadIdx.x] = 0;
    int e4 = blockIdx.x * blockDim.x + threadIdx.x;
    if (e4 >= N_EDGES / 4) return;
    int4 s = ((const int4*)ei)[e4];
    int4 d = ((const int4*)(ei + N_EDGES))[e4];
    int4 sl = ((const int4*)g_slot)[e4];
    g_srcbin[__ldg(&g_off[d.x]) + sl.x] = s.x;
    g_srcbin[__ldg(&g_off[d.y]) + sl.y] = s.y;
    g_srcbin[__ldg(&g_off[d.z]) + sl.z] = s.z;
    g_srcbin[__ldg(&g_off[d.w]) + sl.w] = s.w;
}

// ---------------------------------------------------------------------------
// GEMM1 (HMMA, A in plain fp16, W split hi/lo -> 2 MMAs/tile):
//   g_h16 = fp16((x @ Wc) * dinv[row])
// Runs after scan (needs dinv), overlapping k_bin on the other stream.
// ---------------------------------------------------------------------------
__global__ __launch_bounds__(256) void k_gemm1_mma(const float* __restrict__ x) {
    int tid = threadIdx.x, wid = tid >> 5, lane = tid & 31;
    int rowbase = blockIdx.x * 128 + wid * 16;
    int r0 = rowbase + (lane >> 2);
    int r1 = r0 + 8;
    int kc = (lane & 3) * 2;
    bool v0 = r0 < N_NODES, v1 = r1 < N_NODES;

    float acc[8][4];
    #pragma unroll
    for (int nt = 0; nt < 8; nt++)
        #pragma unroll
        for (int i = 0; i < 4; i++) acc[nt][i] = 0.0f;

    const float2 z2 = make_float2(0.f, 0.f);
    #pragma unroll
    for (int kt = 0; kt < 8; kt++) {
        int k0 = kt * 16 + kc;
        float2 x00 = v0 ? *(const float2*)&x[(size_t)r0 * IN_DIM + k0] : z2;
        float2 x02 = v0 ? *(const float2*)&x[(size_t)r0 * IN_DIM + k0 + 8] : z2;
        float2 x10 = v1 ? *(const float2*)&x[(size_t)r1 * IN_DIM + k0] : z2;
        float2 x12 = v1 ? *(const float2*)&x[(size_t)r1 * IN_DIM + k0 + 8] : z2;
        __half2 h0 = __floats2half2_rn(x00.x, x00.y);
        __half2 h1 = __floats2half2_rn(x10.x, x10.y);
        __half2 h2 = __floats2half2_rn(x02.x, x02.y);
        __half2 h3 = __floats2half2_rn(x12.x, x12.y);
        uint32_t a0 = *reinterpret_cast<uint32_t*>(&h0);
        uint32_t a1 = *reinterpret_cast<uint32_t*>(&h1);
        uint32_t a2 = *reinterpret_cast<uint32_t*>(&h2);
        uint32_t a3 = *reinterpret_cast<uint32_t*>(&h3);
        const uint2* Bh = &g_WcB_hi[kt * 256 + lane];
        const uint2* Bl = &g_WcB_lo[kt * 256 + lane];
        #pragma unroll
        for (int nt = 0; nt < 8; nt++) {
            uint2 bh = Bh[nt * 32];
            uint2 bl = Bl[nt * 32];
            mma_f16(acc[nt], a0, a1, a2, a3, bh.x, bh.y);
            mma_f16(acc[nt], a0, a1, a2, a3, bl.x, bl.y);
        }
    }

    if (v0) {
        float dv = g_dinv[r0];
        #pragma unroll
        for (int nt = 0; nt < 8; nt++) {
            int c = nt * 8 + kc;
            __half2 hv = __floats2half2_rn(acc[nt][0] * dv, acc[nt][1] * dv);
            *(__half2*)&g_h16[(size_t)r0 * HID_DIM + c] = hv;
        }
    }
    if (v1) {
        float dv = g_dinv[r1];
        #pragma unroll
        for (int nt = 0; nt < 8; nt++) {
            int c = nt * 8 + kc;
            __half2 hv = __floats2half2_rn(acc[nt][2] * dv, acc[nt][3] * dv);
            *(__half2*)&g_h16[(size_t)r1 * HID_DIM + c] = hv;
        }
    }
}

// ---------------------------------------------------------------------------
// CSR aggregate (atomic-free, fp16 gather) + fused bias/relu:
// agg16[n] = fp16(relu((sum_{src} h16[src] + h16[n]) * dinv[n] + bc))
// Also clears g_cnt[node] for the next replay (after the warp-wide read).
// ---------------------------------------------------------------------------
__global__ __launch_bounds__(256) void k_aggregate(const float* __restrict__ bc) {
    int tid = threadIdx.x;
    int node = blockIdx.x * 32 + (tid >> 3);
    int sub = tid & 7;
    if (node >= N_NODES) return;
    unsigned gmask = 0xffu << ((tid & 31) & ~7);  // own 8-thread group

    int beg = g_off[node];
    int cnt = g_cnt[node];
    if (sub == 0) g_cnt[node] = 0;  // zero-at-exit for next replay
    int end = beg + cnt;

    float acc[8];
    {   // self-loop term
        uint4 hv = *(const uint4*)&g_h16[(size_t)node * HID_DIM + sub * 8];
        const __half2* hp = (const __half2*)&hv;
        #pragma unroll
        for (int q = 0; q < 4; q++) {
            float2 f = __half22float2(hp[q]);
            acc[q * 2] = f.x; acc[q * 2 + 1] = f.y;
        }
    }

    int p = beg;
    int full_end = beg + (cnt & ~7);
    for (; p < full_end; p += 8) {
        int mysrc = g_srcbin[p + sub];
        #pragma unroll
        for (int j = 0; j < 8; j++) {
            int s = __shfl_sync(gmask, mysrc, j, 8);
            uint4 hv = *(const uint4*)&g_h16[(size_t)s * HID_DIM + sub * 8];
            const __half2* hp = (const __half2*)&hv;
            #pragma unroll
            for (int q = 0; q < 4; q++) {
                float2 f = __half22float2(hp[q]);
                acc[q * 2] += f.x; acc[q * 2 + 1] += f.y;
            }
        }
    }
    if (p < end) {
        int mye = p + sub;
        int mysrc = (mye < end) ? g_srcbin[mye] : 0;
        int m = end - p;
        #pragma unroll
        for (int j = 0; j < 8; j++) {
            if (j < m) {
                int s = __shfl_sync(gmask, mysrc, j, 8);
                uint4 hv = *(const uint4*)&g_h16[(size_t)s * HID_DIM + sub * 8];
                const __half2* hp = (const __half2*)&hv;
                #pragma unroll
                for (int q = 0; q < 4; q++) {
                    float2 f = __half22float2(hp[q]);
                    acc[q * 2] += f.x; acc[q * 2 + 1] += f.y;
                }
            }
        }
    }

    float dv = g_dinv[node];
    float4 b0 = *(const float4*)&bc[sub * 8];
    float4 b1 = *(const float4*)&bc[sub * 8 + 4];
    float r[8];
    r[0] = fmaxf(acc[0] * dv + b0.x, 0.f);
    r[1] = fmaxf(acc[1] * dv + b0.y, 0.f);
    r[2] = fmaxf(acc[2] * dv + b0.z, 0.f);
    r[3] = fmaxf(acc[3] * dv + b0.w, 0.f);
    r[4] = fmaxf(acc[4] * dv + b1.x, 0.f);
    r[5] = fmaxf(acc[5] * dv + b1.y, 0.f);
    r[6] = fmaxf(acc[6] * dv + b1.z, 0.f);
    r[7] = fmaxf(acc[7] * dv + b1.w, 0.f);
    uint4 ov;
    __half2 p0 = __floats2half2_rn(r[0], r[1]);
    __half2 p1 = __floats2half2_rn(r[2], r[3]);
    __half2 p2 = __floats2half2_rn(r[4], r[5]);
    __half2 p3 = __floats2half2_rn(r[6], r[7]);
    ov.x = *reinterpret_cast<uint32_t*>(&p0);
    ov.y = *reinterpret_cast<uint32_t*>(&p1);
    ov.z = *reinterpret_cast<uint32_t*>(&p2);
    ov.w = *reinterpret_cast<uint32_t*>(&p3);
    *(uint4*)&g_agg16[(size_t)node * HID_DIM + sub * 8] = ov;
}

// ---------------------------------------------------------------------------
// GEMM2 (HMMA f16 2-product): out = agg16 @ Wl + bl
// ---------------------------------------------------------------------------
__global__ __launch_bounds__(256) void k_gemm2_mma(const float* __restrict__ bl,
                                                   float* __restrict__ out) {
    int tid = threadIdx.x, wid = tid >> 5, lane = tid & 31;
    int rowbase = blockIdx.x * 128 + wid * 16;
    int r0 = rowbase + (lane >> 2);
    int r1 = r0 + 8;
    int kc = (lane & 3) * 2;
    bool v0 = r0 < N_NODES, v1 = r1 < N_NODES;

    float acc[16][4];
    #pragma unroll
    for (int nt = 0; nt < 16; nt++)
        #pragma unroll
        for (int i = 0; i < 4; i++) acc[nt][i] = 0.0f;

    #pragma unroll
    for (int kt = 0; kt < 4; kt++) {
        int k0 = kt * 16 + kc;
        uint32_t a0 = 0, a1 = 0, a2 = 0, a3 = 0;
        if (v0) {
            a0 = *(const uint32_t*)&g_agg16[(size_t)r0 * HID_DIM + k0];
            a2 = *(const uint32_t*)&g_agg16[(size_t)r0 * HID_DIM + k0 + 8];
        }
        if (v1) {
            a1 = *(const uint32_t*)&g_agg16[(size_t)r1 * HID_DIM + k0];
            a3 = *(const uint32_t*)&g_agg16[(size_t)r1 * HID_DIM + k0 + 8];
        }
        const uint2* Bh = &g_WlB_hi[kt * 512 + lane];
        const uint2* Bl = &g_WlB_lo[kt * 512 + lane];
        #pragma unroll
        for (int nt = 0; nt < 16; nt++) {
            uint2 bh = Bh[nt * 32];
            uint2 blf = Bl[nt * 32];
            mma_f16(acc[nt], a0, a1, a2, a3, bh.x, bh.y);
            mma_f16(acc[nt], a0, a1, a2, a3, blf.x, blf.y);
        }
    }

    if (v0) {
        #pragma unroll
        for (int nt = 0; nt < 16; nt++) {
            int c = nt * 8 + kc;
            float2 b = *(const float2*)&bl[c];
            *(float2*)&out[(size_t)r0 * OUT_DIM + c] =
                make_float2(acc[nt][0] + b.x, acc[nt][1] + b.y);
        }
    }
    if (v1) {
        #pragma unroll
        for (int nt = 0; nt < 16; nt++) {
            int c = nt * 8 + kc;
            float2 b = *(const float2*)&bl[c];
            *(float2*)&out[(size_t)r1 * OUT_DIM + c] =
                make_float2(acc[nt][2] + b.x, acc[nt][3] + b.y);
        }
    }
}

// ---------------------------------------------------------------------------
// Launch — R10's proven fork/join shape, minus k_zero:
//   stream0: count -> scan -> bin -> [join gemm1] aggregate -> gemm2
//   sB:      [fork] initw -> [wait scan] gemm1
// ---------------------------------------------------------------------------
extern "C" void kernel_launch(void* const* d_in, const int* in_sizes, int n_in,
                              void* d_out, int out_size) {
    const float* x  = (const float*)d_in[0];
    const int*   ei = (const int*)d_in[1];
    const float* Wc = (const float*)d_in[2];
    const float* bc = (const float*)d_in[3];
    const float* Wl = (const float*)d_in[4];
    const float* bl = (const float*)d_in[5];
    float* out = (float*)d_out;

    static cudaStream_t sB = nullptr;
    static cudaEvent_t evFork, evScan, evB;
    if (sB == nullptr) {
        cudaStreamCreateWithFlags(&sB, cudaStreamNonBlocking);
        cudaEventCreateWithFlags(&evFork, cudaEventDisableTiming);
        cudaEventCreateWithFlags(&evScan, cudaEventDisableTiming);
        cudaEventCreateWithFlags(&evB, cudaEventDisableTiming);
    }

    int grid = (N_NODES + 127) / 128;  // 782

    // Fork sB off stream 0
    cudaEventRecord(evFork, 0);
    cudaStreamWaitEvent(sB, evFork, 0);

    // sB: weight packing (independent of CSR chain)
    k_initw<<<16, 256, 0, sB>>>(Wc, Wl);

    // stream0: CSR chain (g_cnt/g_bsum arrive zeroed via zero-at-exit)
    k_count<<<(N_EDGES / 4 + 255) / 256, 256>>>(ei + N_EDGES);
    k_scan_fused<<<SCAN_NB, 256>>>();

    // gemm1 on sB once dinv is ready; bin runs concurrently on stream0
    cudaEventRecord(evScan, 0);
    cudaStreamWaitEvent(sB, evScan, 0);
    k_gemm1_mma<<<grid, 256, 0, sB>>>(x);
    cudaEventRecord(evB, sB);

    k_bin<<<(N_EDGES / 4 + 255) / 256, 256>>>(ei);

    // Join: aggregate needs bin (stream0) AND gemm1 (sB)
    cudaStreamWaitEvent(0, evB, 0);
    k_aggregate<<<(N_NODES + 31) / 32, 256>>>(bc);
    k_gemm2_mma<<<grid, 256>>>(bl, out);
}